// round 7
// baseline (speedup 1.0000x reference)
#include <cuda_runtime.h>
#include <cuda_fp16.h>
#include <cstdint>
#include <cstddef>

// ---------------------------------------------------------------- problem shape
#define BATCH 4
#define SEQ   2048
#define NPREV 8
#define DIM   1024
#define HEADS 16
#define HDIM  64
#define TOKENS (BATCH * SEQ)           // 8192
#define KVROWS (TOKENS * NPREV)        // 65536

// ---------------------------------------------------------------- scratch
__device__ __half g_cur16[(size_t)TOKENS * DIM];
__device__ __half g_wq[(size_t)DIM * DIM];
__device__ __half g_wv[(size_t)DIM * DIM];
__device__ __half g_wo[(size_t)DIM * DIM];
__device__ __half g_wkt[(size_t)HEADS * DIM * HDIM];     // [h][j:1024][d:64] = Wk[h*64+d][j]
__device__ __half g_q16[(size_t)TOKENS * DIM];
__device__ __half g_qp [(size_t)HEADS * TOKENS * DIM];   // [h][t][j]
__device__ __half g_hmix[(size_t)HEADS * TOKENS * DIM];  // [h][t][j]
__device__ __half g_o16[(size_t)TOKENS * DIM];

// ---------------------------------------------------------------- helpers
__device__ __forceinline__ uint32_t smem_u32(const void* p) {
    uint32_t a;
    asm("{ .reg .u64 t; cvta.to.shared.u64 t, %1; cvt.u32.u64 %0, t; }" : "=r"(a) : "l"(p));
    return a;
}
__device__ __forceinline__ uint32_t swz(uint32_t off) { return off ^ ((off >> 3) & 0x70); }

__device__ __forceinline__ void cpasync16(uint32_t s, const void* g) {
    asm volatile("cp.async.cg.shared.global [%0], [%1], 16;" :: "r"(s), "l"(g));
}
__device__ __forceinline__ void cp_commit() {
    asm volatile("cp.async.commit_group;" ::: "memory");
}
template <int N>
__device__ __forceinline__ void cp_wait() {
    asm volatile("cp.async.wait_group %0;" :: "n"(N) : "memory");
}

__device__ __forceinline__ void ldsm_x4(uint32_t& r0, uint32_t& r1, uint32_t& r2, uint32_t& r3,
                                        uint32_t addr) {
    asm volatile("ldmatrix.sync.aligned.m8n8.x4.shared.b16 {%0,%1,%2,%3}, [%4];"
                 : "=r"(r0), "=r"(r1), "=r"(r2), "=r"(r3) : "r"(addr));
}

__device__ __forceinline__ void mma16816_f16(float* d, const uint32_t* a, const uint32_t* b) {
    asm volatile(
        "mma.sync.aligned.m16n8k16.row.col.f32.f16.f16.f32 "
        "{%0,%1,%2,%3}, {%4,%5,%6,%7}, {%8,%9}, {%0,%1,%2,%3};"
        : "+f"(d[0]), "+f"(d[1]), "+f"(d[2]), "+f"(d[3])
        : "r"(a[0]), "r"(a[1]), "r"(a[2]), "r"(a[3]), "r"(b[0]), "r"(b[1]));
}

// ================================================================ GEMM A: full 1024-K
#define GBM 128
#define GBN 128
#define NCHUNK (DIM / 64)                 // 16
#define MAT_BYTES (128 * 128)
#define STAGE_BYTES (2 * MAT_BYTES)
#define NSTAGE 3
#define SMEM_DYN (NSTAGE * STAGE_BYTES)   // 96 KB

__device__ __forceinline__ void load_stage(
    uint32_t sbase, int tid, const char* A, const char* B,
    long long m0, long long n0, int chunk)
{
    const long long kbyte = (long long)chunk * 128;
#pragma unroll
    for (int i = 0; i < 4; i++) {
        const int u  = tid + i * 256;
        const int r  = u >> 3;
        const int c8 = u & 7;
        const uint32_t so = swz((uint32_t)(r * 128 + c8 * 16));
        cpasync16(sbase + so,             A + (m0 + r) * (DIM * 2) + kbyte + c8 * 16);
        cpasync16(sbase + MAT_BYTES + so, B + (n0 + r) * (DIM * 2) + kbyte + c8 * 16);
    }
}

template <bool F16OUT>
__global__ __launch_bounds__(256, 2) void gemm_f16(
    const __half* __restrict__ A, const __half* __restrict__ B,
    void* __restrict__ Cout, const float* __restrict__ addend)
{
    extern __shared__ char dynsmem[];
    const uint32_t base = smem_u32(dynsmem);

    const int tid = threadIdx.x, lane = tid & 31, wid = tid >> 5;
    const int warp_m = wid & 3, warp_n = wid >> 2;
    const long long m0 = (long long)blockIdx.y * GBM;
    const long long n0 = (long long)blockIdx.x * GBN;
    const char* pA = (const char*)A;
    const char* pB = (const char*)B;

    float acc[2][8][4];
#pragma unroll
    for (int mt = 0; mt < 2; mt++)
#pragma unroll
        for (int nt = 0; nt < 8; nt++)
#pragma unroll
            for (int j = 0; j < 4; j++) acc[mt][nt][j] = 0.f;

    load_stage(base, tid, pA, pB, m0, n0, 0);
    cp_commit();
    load_stage(base + STAGE_BYTES, tid, pA, pB, m0, n0, 1);
    cp_commit();

    const int a_row = warp_m * 32 + (lane & 15);
    const int a_cofs = (lane & 16) ? 16 : 0;
    const int b_row = warp_n * 64 + (lane & 7) + ((lane & 16) ? 8 : 0);
    const int b_cofs = (lane & 8) ? 16 : 0;

    for (int c = 0; c < NCHUNK; ++c) {
        if (c + 2 < NCHUNK) cp_wait<1>(); else cp_wait<0>();
        __syncthreads();
        if (c + 2 < NCHUNK) {
            load_stage(base + ((c + 2) % NSTAGE) * STAGE_BYTES, tid, pA, pB, m0, n0, c + 2);
            cp_commit();
        }
        const uint32_t sA = base + (c % NSTAGE) * STAGE_BYTES;
        const uint32_t sB = sA + MAT_BYTES;
#pragma unroll
        for (int s = 0; s < 4; s++) {
            uint32_t af[2][4], bf[8][2];
#pragma unroll
            for (int mt = 0; mt < 2; mt++) {
                const uint32_t off = swz((uint32_t)((a_row + mt * 16) * 128 + s * 32 + a_cofs));
                ldsm_x4(af[mt][0], af[mt][1], af[mt][2], af[mt][3], sA + off);
            }
#pragma unroll
            for (int np = 0; np < 4; np++) {
                const uint32_t off = swz((uint32_t)((b_row + np * 16) * 128 + s * 32 + b_cofs));
                uint32_t r0, r1, r2, r3;
                ldsm_x4(r0, r1, r2, r3, sB + off);
                bf[np * 2][0] = r0;     bf[np * 2][1] = r1;
                bf[np * 2 + 1][0] = r2; bf[np * 2 + 1][1] = r3;
            }
#pragma unroll
            for (int mt = 0; mt < 2; mt++)
#pragma unroll
                for (int nt = 0; nt < 8; nt++)
                    mma16816_f16(acc[mt][nt], af[mt], bf[nt]);
        }
        __syncthreads();
    }

    const int g = lane >> 2, t = lane & 3;
#pragma unroll
    for (int mt = 0; mt < 2; mt++)
#pragma unroll
        for (int half = 0; half < 2; half++) {
            const long long row = m0 + warp_m * 32 + mt * 16 + g + half * 8;
            const long long colbase = n0 + warp_n * 64;
            if (F16OUT) {
                __half* crow = (__half*)Cout + row * DIM + colbase;
#pragma unroll
                for (int nt = 0; nt < 8; nt++)
                    *reinterpret_cast<__half2*>(crow + nt * 8 + 2 * t) =
                        __floats2half2_rn(acc[mt][nt][half * 2], acc[mt][nt][half * 2 + 1]);
            } else {
                float* crow = (float*)Cout + row * DIM + colbase;
                const float* arow = addend + row * DIM + colbase;
#pragma unroll
                for (int nt = 0; nt < 8; nt++) {
                    float2 v;
                    v.x = acc[mt][nt][half * 2];
                    v.y = acc[mt][nt][half * 2 + 1];
                    const float2 a = *reinterpret_cast<const float2*>(arow + nt * 8 + 2 * t);
                    v.x += a.x; v.y += a.y;
                    *reinterpret_cast<float2*>(crow + nt * 8 + 2 * t) = v;
                }
            }
        }
}

// ================================================================ GEMM B: qp v2
// CTA = (head h, M-tile 128). Load A (q slice, 16KB) once; stream 8 B-tiles of
// wkt_h double-buffered; write qp[h][m0..][:]. K=64 single chunk.
__global__ __launch_bounds__(256, 2) void gemm_qp()
{
    __shared__ char sm[49152];                 // A 16KB + B 2x16KB
    const uint32_t sA = smem_u32(sm);

    const int tid = threadIdx.x, lane = tid & 31, wid = tid >> 5;
    const int warp_m = wid & 3, warp_n = wid >> 2;
    const int h = blockIdx.x;
    const long long m0 = (long long)blockIdx.y * 128;

    const char* Ab = (const char*)g_cur16;     // placeholder type; real A below
    Ab = (const char*)g_q16 + m0 * (DIM * 2) + h * 128;
    const char* Bb = (const char*)g_wkt + (size_t)h * (DIM * HDIM * 2);
    __half* C = g_qp + ((size_t)h * TOKENS + m0) * DIM;

    // A: 128 rows x 128B (q columns h*64..h*64+63)
#pragma unroll
    for (int i = 0; i < 4; i++) {
        const int u = tid + i * 256;
        const int r = u >> 3, c8 = u & 7;
        const uint32_t so = swz((uint32_t)(r * 128 + c8 * 16));
        cpasync16(sA + so, Ab + (long long)r * (DIM * 2) + c8 * 16);
    }

    auto loadB = [&](int bt, int buf) {
        const uint32_t sb = sA + 16384 + buf * 16384;
        const char* Bt = Bb + (size_t)bt * 128 * 128;   // 128 j-rows x 128B
#pragma unroll
        for (int i = 0; i < 4; i++) {
            const int u = tid + i * 256;
            const int r = u >> 3, c8 = u & 7;
            const uint32_t so = swz((uint32_t)(r * 128 + c8 * 16));
            cpasync16(sb + so, Bt + r * 128 + c8 * 16);
        }
    };
    loadB(0, 0); cp_commit();
    loadB(1, 1); cp_commit();

    const int a_row = warp_m * 32 + (lane & 15);
    const int a_cofs = (lane & 16) ? 16 : 0;
    const int b_row = warp_n * 64 + (lane & 7) + ((lane & 16) ? 8 : 0);
    const int b_cofs = (lane & 8) ? 16 : 0;
    const int g = lane >> 2, t4 = lane & 3;

    for (int bt = 0; bt < 8; bt++) {
        if (bt < 7) cp_wait<1>(); else cp_wait<0>();
        __syncthreads();

        const uint32_t sB = sA + 16384 + (bt & 1) * 16384;
        float acc[2][8][4];
#pragma unroll
        for (int mt = 0; mt < 2; mt++)
#pragma unroll
            for (int nt = 0; nt < 8; nt++)
#pragma unroll
                for (int j = 0; j < 4; j++) acc[mt][nt][j] = 0.f;

#pragma unroll
        for (int s = 0; s < 4; s++) {
            uint32_t af[2][4], bf[8][2];
#pragma unroll
            for (int mt = 0; mt < 2; mt++) {
                const uint32_t off = swz((uint32_t)((a_row + mt * 16) * 128 + s * 32 + a_cofs));
                ldsm_x4(af[mt][0], af[mt][1], af[mt][2], af[mt][3], sA + off);
            }
#pragma unroll
            for (int np = 0; np < 4; np++) {
                const uint32_t off = swz((uint32_t)((b_row + np * 16) * 128 + s * 32 + b_cofs));
                uint32_t r0, r1, r2, r3;
                ldsm_x4(r0, r1, r2, r3, sB + off);
                bf[np * 2][0] = r0;     bf[np * 2][1] = r1;
                bf[np * 2 + 1][0] = r2; bf[np * 2 + 1][1] = r3;
            }
#pragma unroll
            for (int mt = 0; mt < 2; mt++)
#pragma unroll
                for (int nt = 0; nt < 8; nt++)
                    mma16816_f16(acc[mt][nt], af[mt], bf[nt]);
        }
        __syncthreads();                        // buffer fully consumed
        if (bt + 2 < 8) { loadB(bt + 2, bt & 1); cp_commit(); }

        // store this N-tile (cols bt*128 + warp_n*64 + ...)
#pragma unroll
        for (int mt = 0; mt < 2; mt++)
#pragma unroll
            for (int half = 0; half < 2; half++) {
                const long long row = warp_m * 32 + mt * 16 + g + half * 8;
                __half* crow = C + row * DIM + bt * 128 + warp_n * 64;
#pragma unroll
                for (int nt = 0; nt < 8; nt++)
                    *reinterpret_cast<__half2*>(crow + nt * 8 + 2 * t4) =
                        __floats2half2_rn(acc[mt][nt][half * 2], acc[mt][nt][half * 2 + 1]);
            }
    }
}

// ================================================================ GEMM C: vproj
// head h: o[:, h*64:+64] = hmix_h[8192,1024] @ Wv[h*64:+64, :]^T. 3-stage pipeline.
#define VP_STAGE (128 * 128 + 64 * 128)      // 24KB
#define VP_SMEM (3 * VP_STAGE)               // 72KB

__global__ __launch_bounds__(256, 2) void gemm_vproj()
{
    extern __shared__ char dynsmem[];
    const uint32_t base = smem_u32(dynsmem);

    const int tid = threadIdx.x, lane = tid & 31, wid = tid >> 5;
    const int h = blockIdx.z;
    const long long m0 = (long long)blockIdx.y * 128;

    const char* A = (const char*)(g_hmix + (size_t)h * TOKENS * DIM);
    const char* B = (const char*)(g_wv + (size_t)h * HDIM * DIM);
    __half* C = g_o16 + (size_t)h * HDIM;

    auto load_vp = [&](int stage, int chunk) {
        const uint32_t sb = base + stage * VP_STAGE;
        const long long kbyte = (long long)chunk * 128;
#pragma unroll
        for (int i = 0; i < 4; i++) {
            const int u = tid + i * 256;
            const int r = u >> 3, c8 = u & 7;
            const uint32_t so = swz((uint32_t)(r * 128 + c8 * 16));
            cpasync16(sb + so, A + (m0 + r) * (DIM * 2) + kbyte + c8 * 16);
        }
#pragma unroll
        for (int i = 0; i < 2; i++) {
            const int u = tid + i * 256;
            const int r = u >> 3, c8 = u & 7;
            const uint32_t so = swz((uint32_t)(r * 128 + c8 * 16));
            cpasync16(sb + 128 * 128 + so, B + r * (DIM * 2) + kbyte + c8 * 16);
        }
    };

    float acc[8][4];
#pragma unroll
    for (int nt = 0; nt < 8; nt++)
#pragma unroll
        for (int j = 0; j < 4; j++) acc[nt][j] = 0.f;

    load_vp(0, 0); cp_commit();
    load_vp(1, 1); cp_commit();

    const int a_row = wid * 16 + (lane & 15);
    const int a_cofs = (lane & 16) ? 16 : 0;
    const int b_row = (lane & 7) + ((lane & 16) ? 8 : 0);
    const int b_cofs = (lane & 8) ? 16 : 0;

    for (int c = 0; c < NCHUNK; ++c) {
        if (c + 2 < NCHUNK) cp_wait<1>(); else cp_wait<0>();
        __syncthreads();
        if (c + 2 < NCHUNK) { load_vp((c + 2) % 3, c + 2); cp_commit(); }

        const uint32_t sA = base + (c % 3) * VP_STAGE;
        const uint32_t sB = sA + 128 * 128;
#pragma unroll
        for (int s = 0; s < 4; s++) {
            uint32_t af[4], bf[8][2];
            {
                const uint32_t off = swz((uint32_t)(a_row * 128 + s * 32 + a_cofs));
                ldsm_x4(af[0], af[1], af[2], af[3], sA + off);
            }
#pragma unroll
            for (int np = 0; np < 4; np++) {
                const uint32_t off = swz((uint32_t)((b_row + np * 16) * 128 + s * 32 + b_cofs));
                uint32_t r0, r1, r2, r3;
                ldsm_x4(r0, r1, r2, r3, sB + off);
                bf[np * 2][0] = r0;     bf[np * 2][1] = r1;
                bf[np * 2 + 1][0] = r2; bf[np * 2 + 1][1] = r3;
            }
#pragma unroll
            for (int nt = 0; nt < 8; nt++)
                mma16816_f16(acc[nt], af, bf[nt]);
        }
        __syncthreads();
    }

    const int g = lane >> 2, t = lane & 3;
#pragma unroll
    for (int half = 0; half < 2; half++) {
        const long long row = m0 + wid * 16 + g + half * 8;
        __half* crow = C + row * DIM;
#pragma unroll
        for (int nt = 0; nt < 8; nt++)
            *reinterpret_cast<__half2*>(crow + nt * 8 + 2 * t) =
                __floats2half2_rn(acc[nt][half * 2], acc[nt][half * 2 + 1]);
    }
}

// ================================================================ converts
__global__ __launch_bounds__(256) void tohalf_kernel(
    const float4* __restrict__ x, __half2* __restrict__ y, int n4)
{
    const int i = blockIdx.x * blockDim.x + threadIdx.x;
    if (i >= n4) return;
    const float4 v = x[i];
    y[i * 2 + 0] = __floats2half2_rn(v.x, v.y);
    y[i * 2 + 1] = __floats2half2_rn(v.z, v.w);
}

// wkt[h][j][d] = Wk[h*64+d][j]
__global__ __launch_bounds__(256) void wkt_kernel(const float* __restrict__ Wk)
{
    const int idx = blockIdx.x * blockDim.x + threadIdx.x;   // 1M
    const int h = idx >> 16;
    const int j = (idx >> 6) & 1023;
    const int d = idx & 63;
    g_wkt[idx] = __float2half(Wk[(h * HDIM + d) * DIM + j]);
}

// ================================================================ fused attention
// One CTA per token, 512 threads, warp w = head w. Reads fp32 history directly.
__global__ __launch_bounds__(512) void attn_fused(const float* __restrict__ hist)
{
    __shared__ __half2 hist2[NPREV * 512];      // 16KB

    const int t = blockIdx.x;
    const int tid = threadIdx.x;
    const int lane = tid & 31;
    const int h = tid >> 5;                     // 0..15

    // load + convert history for this token (8192 floats)
    {
        const float4* src = reinterpret_cast<const float4*>(hist + (size_t)t * NPREV * DIM);
#pragma unroll
        for (int i = 0; i < 4; i++) {
            const int idx = tid + i * 512;      // 0..2047
            const float4 v = src[idx];
            hist2[idx * 2 + 0] = __floats2half2_rn(v.x, v.y);
            hist2[idx * 2 + 1] = __floats2half2_rn(v.z, v.w);
        }
    }
    __syncthreads();

    const __half2* qp2 = reinterpret_cast<const __half2*>(g_qp + ((size_t)h * TOKENS + t) * DIM);
    __half2 q2[16];
#pragma unroll
    for (int i = 0; i < 16; i++) q2[i] = qp2[lane + 32 * i];

    float logits[NPREV];
#pragma unroll
    for (int n = 0; n < NPREV; n++) {
        float p = 0.f;
#pragma unroll
        for (int i = 0; i < 16; i++) {
            const float2 a = __half22float2(q2[i]);
            const float2 b = __half22float2(hist2[n * 512 + lane + 32 * i]);
            p += a.x * b.x + a.y * b.y;
        }
#pragma unroll
        for (int off = 16; off > 0; off >>= 1)
            p += __shfl_xor_sync(0xFFFFFFFFu, p, off);
        logits[n] = p * 0.125f;
    }

    float mx = logits[0];
#pragma unroll
    for (int n = 1; n < NPREV; n++) mx = fmaxf(mx, logits[n]);
    float w[NPREV], den = 0.f;
#pragma unroll
    for (int n = 0; n < NPREV; n++) { w[n] = __expf(logits[n] - mx); den += w[n]; }
    const float inv = 1.f / den;
#pragma unroll
    for (int n = 0; n < NPREV; n++) w[n] *= inv;

    __half2* out2 = reinterpret_cast<__half2*>(g_hmix + ((size_t)h * TOKENS + t) * DIM);
#pragma unroll
    for (int i = 0; i < 16; i++) {
        float sx = 0.f, sy = 0.f;
#pragma unroll
        for (int n = 0; n < NPREV; n++) {
            const float2 b = __half22float2(hist2[n * 512 + lane + 32 * i]);
            sx += w[n] * b.x;
            sy += w[n] * b.y;
        }
        out2[lane + 32 * i] = __floats2half2_rn(sx, sy);
    }
}

// ================================================================ launch
extern "C" void kernel_launch(void* const* d_in, const int* in_sizes, int n_in,
                              void* d_out, int out_size)
{
    const float* current = (const float*)d_in[0];
    const float* history = (const float*)d_in[1];
    const float* Wq      = (const float*)d_in[2];
    const float* Wk      = (const float*)d_in[3];
    const float* Wv      = (const float*)d_in[4];
    const float* Wo      = (const float*)d_in[5];
    float*       out     = (float*)d_out;

    __half *cur16, *wq, *wv, *wo, *q16, *o16;
    cudaGetSymbolAddress((void**)&cur16, g_cur16);
    cudaGetSymbolAddress((void**)&wq,    g_wq);
    cudaGetSymbolAddress((void**)&wv,    g_wv);
    cudaGetSymbolAddress((void**)&wo,    g_wo);
    cudaGetSymbolAddress((void**)&q16,   g_q16);
    cudaGetSymbolAddress((void**)&o16,   g_o16);

    cudaFuncSetAttribute(gemm_f16<true>,  cudaFuncAttributeMaxDynamicSharedMemorySize, SMEM_DYN);
    cudaFuncSetAttribute(gemm_f16<false>, cudaFuncAttributeMaxDynamicSharedMemorySize, SMEM_DYN);
    cudaFuncSetAttribute(gemm_vproj,      cudaFuncAttributeMaxDynamicSharedMemorySize, VP_SMEM);

    const size_t WN = (size_t)DIM * DIM;

    // converts (no history convert — attn_fused reads fp32 directly)
    tohalf_kernel<<<TOKENS * DIM / 4 / 256, 256>>>((const float4*)current, (__half2*)cur16,
                                                   TOKENS * DIM / 4);
    tohalf_kernel<<<(int)(WN / 4 / 256), 256>>>((const float4*)Wq, (__half2*)wq, (int)(WN / 4));
    tohalf_kernel<<<(int)(WN / 4 / 256), 256>>>((const float4*)Wv, (__half2*)wv, (int)(WN / 4));
    tohalf_kernel<<<(int)(WN / 4 / 256), 256>>>((const float4*)Wo, (__half2*)wo, (int)(WN / 4));
    wkt_kernel<<<(int)(WN / 256), 256>>>(Wk);

    // q = current @ Wq^T
    gemm_f16<true><<<dim3(DIM / GBN, TOKENS / GBM), 256, SMEM_DYN>>>(cur16, wq, q16, nullptr);

    // q' per head (A-resident, B-streamed)
    gemm_qp<<<dim3(HEADS, TOKENS / 128), 256>>>();

    // fused logits + softmax + history mix
    attn_fused<<<TOKENS, 512>>>(history);

    // per-head V projection
    gemm_vproj<<<dim3(1, TOKENS / 128, HEADS), 256, VP_SMEM>>>();

    // out = current + o @ Wo^T
    gemm_f16<false><<<dim3(DIM / GBN, TOKENS / GBM), 256, SMEM_DYN>>>(o16, wo, out, current);
}

// round 10
// speedup vs baseline: 1.5318x; 1.5318x over previous
#include <cuda_runtime.h>
#include <cuda_fp16.h>
#include <cstdint>
#include <cstddef>

// ---------------------------------------------------------------- problem shape
#define BATCH 4
#define SEQ   2048
#define NPREV 8
#define DIM   1024
#define HEADS 16
#define HDIM  64
#define TOKENS (BATCH * SEQ)           // 8192
#define KVROWS (TOKENS * NPREV)        // 65536

// ---------------------------------------------------------------- scratch (fp16)
__device__ __half g_cur16 [(size_t)TOKENS * DIM];
__device__ __half g_hist16[(size_t)KVROWS * DIM];
__device__ __half g_w16[4u * DIM * DIM];                 // Wq, Wk, Wv, Wo
__device__ __half g_q16 [(size_t)TOKENS * DIM];
__device__ __half g_k16 [(size_t)KVROWS * DIM];
__device__ __half g_v16 [(size_t)KVROWS * DIM];
__device__ __half g_attn16[(size_t)TOKENS * DIM];

// ---------------------------------------------------------------- helpers
__device__ __forceinline__ uint32_t smem_u32(const void* p) {
    uint32_t a;
    asm("{ .reg .u64 t; cvta.to.shared.u64 t, %1; cvt.u32.u64 %0, t; }" : "=r"(a) : "l"(p));
    return a;
}
__device__ __forceinline__ uint32_t swz(uint32_t off) { return off ^ ((off >> 3) & 0x70); }

__device__ __forceinline__ void cpasync16(uint32_t s, const void* g) {
    asm volatile("cp.async.cg.shared.global [%0], [%1], 16;" :: "r"(s), "l"(g));
}
__device__ __forceinline__ void cp_commit() {
    asm volatile("cp.async.commit_group;" ::: "memory");
}
template <int N>
__device__ __forceinline__ void cp_wait() {
    asm volatile("cp.async.wait_group %0;" :: "n"(N) : "memory");
}

__device__ __forceinline__ void ldsm_x4(uint32_t& r0, uint32_t& r1, uint32_t& r2, uint32_t& r3,
                                        uint32_t addr) {
    asm volatile("ldmatrix.sync.aligned.m8n8.x4.shared.b16 {%0,%1,%2,%3}, [%4];"
                 : "=r"(r0), "=r"(r1), "=r"(r2), "=r"(r3) : "r"(addr));
}

__device__ __forceinline__ void mma16816_f16(float* d, const uint32_t* a, const uint32_t* b) {
    asm volatile(
        "mma.sync.aligned.m16n8k16.row.col.f32.f16.f16.f32 "
        "{%0,%1,%2,%3}, {%4,%5,%6,%7}, {%8,%9}, {%0,%1,%2,%3};"
        : "+f"(d[0]), "+f"(d[1]), "+f"(d[2]), "+f"(d[3])
        : "r"(a[0]), "r"(a[1]), "r"(a[2]), "r"(a[3]), "r"(b[0]), "r"(b[1]));
}

#define GBM 128
#define GBN 128
#define NCHUNK (DIM / 64)                 // 16
#define MAT_BYTES (128 * 128)             // 16 KB

// ================================================================ GEMM: single output
// C[M,1024] = A*B^T (+addend). 128x128 tile, BK=64, 3-stage, 8 warps (32x64 warp tile).
#define STAGE_BYTES (2 * MAT_BYTES)       // 32 KB
#define SMEM_DYN (3 * STAGE_BYTES)        // 96 KB -> 2 CTAs/SM

__device__ __forceinline__ void load_stage(
    uint32_t sbase, int tid, const char* A, const char* B,
    long long m0, long long n0, int chunk)
{
    const long long kbyte = (long long)chunk * 128;
#pragma unroll
    for (int i = 0; i < 4; i++) {
        const int u  = tid + i * 256;
        const int r  = u >> 3;
        const int c8 = u & 7;
        const uint32_t so = swz((uint32_t)(r * 128 + c8 * 16));
        cpasync16(sbase + so,             A + (m0 + r) * (DIM * 2) + kbyte + c8 * 16);
        cpasync16(sbase + MAT_BYTES + so, B + (n0 + r) * (DIM * 2) + kbyte + c8 * 16);
    }
}

template <bool F16OUT>
__global__ __launch_bounds__(256, 2) void gemm_f16(
    const __half* __restrict__ A, const __half* __restrict__ B,
    void* __restrict__ Cout, const float* __restrict__ addend)
{
    extern __shared__ char dynsmem[];
    const uint32_t base = smem_u32(dynsmem);

    const int tid = threadIdx.x, lane = tid & 31, wid = tid >> 5;
    const int warp_m = wid & 3, warp_n = wid >> 2;
    const long long m0 = (long long)blockIdx.y * GBM;
    const long long n0 = (long long)blockIdx.x * GBN;
    const char* pA = (const char*)A;
    const char* pB = (const char*)B;

    float acc[2][8][4];
#pragma unroll
    for (int mt = 0; mt < 2; mt++)
#pragma unroll
        for (int nt = 0; nt < 8; nt++)
#pragma unroll
            for (int j = 0; j < 4; j++) acc[mt][nt][j] = 0.f;

    load_stage(base, tid, pA, pB, m0, n0, 0);
    cp_commit();
    load_stage(base + STAGE_BYTES, tid, pA, pB, m0, n0, 1);
    cp_commit();

    const int a_row = warp_m * 32 + (lane & 15);
    const int a_cofs = (lane & 16) ? 16 : 0;
    const int b_row = warp_n * 64 + (lane & 7) + ((lane & 16) ? 8 : 0);
    const int b_cofs = (lane & 8) ? 16 : 0;

    for (int c = 0; c < NCHUNK; ++c) {
        if (c + 2 < NCHUNK) cp_wait<1>(); else cp_wait<0>();
        __syncthreads();                  // single barrier per chunk (3-stage safe)
        if (c + 2 < NCHUNK) {
            load_stage(base + ((c + 2) % 3) * STAGE_BYTES, tid, pA, pB, m0, n0, c + 2);
            cp_commit();
        }
        const uint32_t sA = base + (c % 3) * STAGE_BYTES;
        const uint32_t sB = sA + MAT_BYTES;
#pragma unroll
        for (int s = 0; s < 4; s++) {
            uint32_t af[2][4], bf[8][2];
#pragma unroll
            for (int mt = 0; mt < 2; mt++) {
                const uint32_t off = swz((uint32_t)((a_row + mt * 16) * 128 + s * 32 + a_cofs));
                ldsm_x4(af[mt][0], af[mt][1], af[mt][2], af[mt][3], sA + off);
            }
#pragma unroll
            for (int np = 0; np < 4; np++) {
                const uint32_t off = swz((uint32_t)((b_row + np * 16) * 128 + s * 32 + b_cofs));
                uint32_t r0, r1, r2, r3;
                ldsm_x4(r0, r1, r2, r3, sB + off);
                bf[np * 2][0] = r0;     bf[np * 2][1] = r1;
                bf[np * 2 + 1][0] = r2; bf[np * 2 + 1][1] = r3;
            }
#pragma unroll
            for (int mt = 0; mt < 2; mt++)
#pragma unroll
                for (int nt = 0; nt < 8; nt++)
                    mma16816_f16(acc[mt][nt], af[mt], bf[nt]);
        }
    }

    const int g = lane >> 2, t = lane & 3;
#pragma unroll
    for (int mt = 0; mt < 2; mt++)
#pragma unroll
        for (int half = 0; half < 2; half++) {
            const long long row = m0 + warp_m * 32 + mt * 16 + g + half * 8;
            const long long colbase = n0 + warp_n * 64;
            if (F16OUT) {
                __half* crow = (__half*)Cout + row * DIM + colbase;
#pragma unroll
                for (int nt = 0; nt < 8; nt++)
                    *reinterpret_cast<__half2*>(crow + nt * 8 + 2 * t) =
                        __floats2half2_rn(acc[mt][nt][half * 2], acc[mt][nt][half * 2 + 1]);
            } else {
                float* crow = (float*)Cout + row * DIM + colbase;
                const float* arow = addend + row * DIM + colbase;
#pragma unroll
                for (int nt = 0; nt < 8; nt++) {
                    float2 v;
                    v.x = acc[mt][nt][half * 2];
                    v.y = acc[mt][nt][half * 2 + 1];
                    const float2 a = *reinterpret_cast<const float2*>(arow + nt * 8 + 2 * t);
                    v.x += a.x; v.y += a.y;
                    *reinterpret_cast<float2*>(crow + nt * 8 + 2 * t) = v;
                }
            }
        }
}

// ================================================================ GEMM: merged K+V
// k = hist @ Wk^T, v = hist @ Wv^T in ONE kernel, sharing A tiles.
// Stage: [A 16KB][Bk 16KB][Bv 16KB] = 48KB, 3 stages = 144KB -> 1 CTA/SM.
#define KV_STAGE (3 * MAT_BYTES)
#define SMEM_KV (3 * KV_STAGE)            // 144 KB

__device__ __forceinline__ void load_stage_kv(
    uint32_t sbase, int tid, const char* A, const char* Bk, const char* Bv,
    long long m0, long long n0, int chunk)
{
    const long long kbyte = (long long)chunk * 128;
#pragma unroll
    for (int i = 0; i < 4; i++) {
        const int u  = tid + i * 256;
        const int r  = u >> 3;
        const int c8 = u & 7;
        const uint32_t so = swz((uint32_t)(r * 128 + c8 * 16));
        const long long gb = (n0 + r) * (DIM * 2) + kbyte + c8 * 16;
        cpasync16(sbase + so,                 A  + (m0 + r) * (DIM * 2) + kbyte + c8 * 16);
        cpasync16(sbase + MAT_BYTES + so,     Bk + gb);
        cpasync16(sbase + 2 * MAT_BYTES + so, Bv + gb);
    }
}

__global__ __launch_bounds__(256, 1) void gemm_kv(
    const __half* __restrict__ A, const __half* __restrict__ Bk,
    const __half* __restrict__ Bv)
{
    extern __shared__ char dynsmem[];
    const uint32_t base = smem_u32(dynsmem);

    const int tid = threadIdx.x, lane = tid & 31, wid = tid >> 5;
    const int warp_m = wid & 3, warp_n = wid >> 2;
    const long long m0 = (long long)blockIdx.y * GBM;
    const long long n0 = (long long)blockIdx.x * GBN;
    const char* pA  = (const char*)A;
    const char* pBk = (const char*)Bk;
    const char* pBv = (const char*)Bv;

    float acck[2][8][4], accv[2][8][4];
#pragma unroll
    for (int mt = 0; mt < 2; mt++)
#pragma unroll
        for (int nt = 0; nt < 8; nt++)
#pragma unroll
            for (int j = 0; j < 4; j++) { acck[mt][nt][j] = 0.f; accv[mt][nt][j] = 0.f; }

    load_stage_kv(base, tid, pA, pBk, pBv, m0, n0, 0);
    cp_commit();
    load_stage_kv(base + KV_STAGE, tid, pA, pBk, pBv, m0, n0, 1);
    cp_commit();

    const int a_row = warp_m * 32 + (lane & 15);
    const int a_cofs = (lane & 16) ? 16 : 0;
    const int b_row = warp_n * 64 + (lane & 7) + ((lane & 16) ? 8 : 0);
    const int b_cofs = (lane & 8) ? 16 : 0;

    for (int c = 0; c < NCHUNK; ++c) {
        if (c + 2 < NCHUNK) cp_wait<1>(); else cp_wait<0>();
        __syncthreads();
        if (c + 2 < NCHUNK) {
            load_stage_kv(base + ((c + 2) % 3) * KV_STAGE, tid, pA, pBk, pBv, m0, n0, c + 2);
            cp_commit();
        }
        const uint32_t sA  = base + (c % 3) * KV_STAGE;
        const uint32_t sBk = sA + MAT_BYTES;
        const uint32_t sBv = sA + 2 * MAT_BYTES;
#pragma unroll
        for (int s = 0; s < 4; s++) {
            uint32_t af[2][4], bk[8][2], bv[8][2];
#pragma unroll
            for (int mt = 0; mt < 2; mt++) {
                const uint32_t off = swz((uint32_t)((a_row + mt * 16) * 128 + s * 32 + a_cofs));
                ldsm_x4(af[mt][0], af[mt][1], af[mt][2], af[mt][3], sA + off);
            }
#pragma unroll
            for (int np = 0; np < 4; np++) {
                const uint32_t off = swz((uint32_t)((b_row + np * 16) * 128 + s * 32 + b_cofs));
                uint32_t r0, r1, r2, r3;
                ldsm_x4(r0, r1, r2, r3, sBk + off);
                bk[np * 2][0] = r0;     bk[np * 2][1] = r1;
                bk[np * 2 + 1][0] = r2; bk[np * 2 + 1][1] = r3;
                ldsm_x4(r0, r1, r2, r3, sBv + off);
                bv[np * 2][0] = r0;     bv[np * 2][1] = r1;
                bv[np * 2 + 1][0] = r2; bv[np * 2 + 1][1] = r3;
            }
#pragma unroll
            for (int mt = 0; mt < 2; mt++)
#pragma unroll
                for (int nt = 0; nt < 8; nt++) {
                    mma16816_f16(acck[mt][nt], af[mt], bk[nt]);
                    mma16816_f16(accv[mt][nt], af[mt], bv[nt]);
                }
        }
    }

    const int g = lane >> 2, t = lane & 3;
#pragma unroll
    for (int mt = 0; mt < 2; mt++)
#pragma unroll
        for (int half = 0; half < 2; half++) {
            const long long row = m0 + warp_m * 32 + mt * 16 + g + half * 8;
            const long long colbase = n0 + warp_n * 64;
            __half* krow = g_k16 + row * DIM + colbase;
            __half* vrow = g_v16 + row * DIM + colbase;
#pragma unroll
            for (int nt = 0; nt < 8; nt++) {
                *reinterpret_cast<__half2*>(krow + nt * 8 + 2 * t) =
                    __floats2half2_rn(acck[mt][nt][half * 2], acck[mt][nt][half * 2 + 1]);
                *reinterpret_cast<__half2*>(vrow + nt * 8 + 2 * t) =
                    __floats2half2_rn(accv[mt][nt][half * 2], accv[mt][nt][half * 2 + 1]);
            }
        }
}

// ================================================================ converts
__global__ __launch_bounds__(256) void tohalf_kernel(
    const float4* __restrict__ x, __half2* __restrict__ y, int n4)
{
    const int i = blockIdx.x * blockDim.x + threadIdx.x;
    if (i >= n4) return;
    const float4 v = x[i];
    y[i * 2 + 0] = __floats2half2_rn(v.x, v.y);
    y[i * 2 + 1] = __floats2half2_rn(v.z, v.w);
}

// all 4 weights in one launch: idx selects which source
__global__ __launch_bounds__(256) void weights_tohalf_kernel(
    const float4* __restrict__ wq, const float4* __restrict__ wk,
    const float4* __restrict__ wv, const float4* __restrict__ wo)
{
    const int i = blockIdx.x * blockDim.x + threadIdx.x;      // 0 .. 4*WN/4-1
    const int which = i >> 18;                                 // WN/4 = 262144 per weight
    const int j = i & 0x3FFFF;
    const float4* src = (which == 0) ? wq : (which == 1) ? wk : (which == 2) ? wv : wo;
    const float4 v = src[j];
    __half2* y = reinterpret_cast<__half2*>(g_w16) + (size_t)i * 2;
    y[0] = __floats2half2_rn(v.x, v.y);
    y[1] = __floats2half2_rn(v.z, v.w);
}

// ================================================================ attention (fp16 I/O)
__global__ __launch_bounds__(256) void attn_kernel()
{
    const int gw   = (blockIdx.x * blockDim.x + threadIdx.x) >> 5;
    const int lane = threadIdx.x & 31;
    const int h = gw & (HEADS - 1);
    const int t = gw >> 4;

    const size_t qoff = (size_t)t * DIM + h * HDIM;
    const float2 qv = __half22float2(reinterpret_cast<const __half2*>(g_q16 + qoff)[lane]);

    float logits[NPREV];
#pragma unroll
    for (int n = 0; n < NPREV; n++) {
        const size_t koff = ((size_t)t * NPREV + n) * DIM + h * HDIM;
        const float2 kv = __half22float2(reinterpret_cast<const __half2*>(g_k16 + koff)[lane]);
        float p = qv.x * kv.x + qv.y * kv.y;
#pragma unroll
        for (int off = 16; off > 0; off >>= 1)
            p += __shfl_xor_sync(0xFFFFFFFFu, p, off);
        logits[n] = p * 0.125f;
    }

    float mx = logits[0];
#pragma unroll
    for (int n = 1; n < NPREV; n++) mx = fmaxf(mx, logits[n]);
    float w[NPREV], den = 0.f;
#pragma unroll
    for (int n = 0; n < NPREV; n++) { w[n] = __expf(logits[n] - mx); den += w[n]; }
    const float inv = 1.f / den;

    float o0 = 0.f, o1 = 0.f;
#pragma unroll
    for (int n = 0; n < NPREV; n++) {
        const size_t voff = ((size_t)t * NPREV + n) * DIM + h * HDIM;
        const float2 vv = __half22float2(reinterpret_cast<const __half2*>(g_v16 + voff)[lane]);
        o0 += w[n] * vv.x;
        o1 += w[n] * vv.y;
    }
    reinterpret_cast<__half2*>(g_attn16 + qoff)[lane] = __floats2half2_rn(o0 * inv, o1 * inv);
}

// ================================================================ launch
extern "C" void kernel_launch(void* const* d_in, const int* in_sizes, int n_in,
                              void* d_out, int out_size)
{
    const float* current = (const float*)d_in[0];
    const float* history = (const float*)d_in[1];
    const float* Wq      = (const float*)d_in[2];
    const float* Wk      = (const float*)d_in[3];
    const float* Wv      = (const float*)d_in[4];
    const float* Wo      = (const float*)d_in[5];
    float*       out     = (float*)d_out;

    __half *cur16, *hist16, *w16, *q16, *k16, *v16, *attn16;
    cudaGetSymbolAddress((void**)&cur16,  g_cur16);
    cudaGetSymbolAddress((void**)&hist16, g_hist16);
    cudaGetSymbolAddress((void**)&w16,    g_w16);
    cudaGetSymbolAddress((void**)&q16,    g_q16);
    cudaGetSymbolAddress((void**)&k16,    g_k16);
    cudaGetSymbolAddress((void**)&v16,    g_v16);
    cudaGetSymbolAddress((void**)&attn16, g_attn16);

    cudaFuncSetAttribute(gemm_f16<true>,  cudaFuncAttributeMaxDynamicSharedMemorySize, SMEM_DYN);
    cudaFuncSetAttribute(gemm_f16<false>, cudaFuncAttributeMaxDynamicSharedMemorySize, SMEM_DYN);
    cudaFuncSetAttribute(gemm_kv,         cudaFuncAttributeMaxDynamicSharedMemorySize, SMEM_KV);

    const size_t WN = (size_t)DIM * DIM;

    // converts
    tohalf_kernel<<<TOKENS * DIM / 4 / 256, 256>>>((const float4*)current, (__half2*)cur16,
                                                   TOKENS * DIM / 4);
    tohalf_kernel<<<(int)((size_t)KVROWS * DIM / 4 / 256), 256>>>(
        (const float4*)history, (__half2*)hist16, (int)((size_t)KVROWS * DIM / 4));
    weights_tohalf_kernel<<<(int)(4 * WN / 4 / 256), 256>>>(
        (const float4*)Wq, (const float4*)Wk, (const float4*)Wv, (const float4*)Wo);

    // q = current @ Wq^T
    gemm_f16<true><<<dim3(DIM / GBN, TOKENS / GBM), 256, SMEM_DYN>>>(
        cur16, w16 + 0 * WN, q16, nullptr);

    // k,v = hist @ Wk^T / Wv^T (merged)
    gemm_kv<<<dim3(DIM / GBN, KVROWS / GBM), 256, SMEM_KV>>>(
        hist16, w16 + 1 * WN, w16 + 2 * WN);

    // attention
    attn_kernel<<<(TOKENS * HEADS) / 8, 256>>>();

    // out = current + attn @ Wo^T
    gemm_f16<false><<<dim3(DIM / GBN, TOKENS / GBM), 256, SMEM_DYN>>>(
        attn16, w16 + 3 * WN, out, current);
}

// round 12
// speedup vs baseline: 1.5936x; 1.0404x over previous
#include <cuda_runtime.h>
#include <cuda_fp16.h>
#include <cstdint>
#include <cstddef>

// ---------------------------------------------------------------- problem shape
#define BATCH 4
#define SEQ   2048
#define NPREV 8
#define DIM   1024
#define HEADS 16
#define HDIM  64
#define TOKENS (BATCH * SEQ)           // 8192
#define KVROWS (TOKENS * NPREV)        // 65536

// ---------------------------------------------------------------- scratch (fp16)
__device__ __half g_cur16 [(size_t)TOKENS * DIM];
__device__ __half g_hist16[(size_t)KVROWS * DIM];
__device__ __half g_w16[4u * DIM * DIM];                 // Wq, Wk, Wv, Wo
__device__ __half g_q16 [(size_t)TOKENS * DIM];
__device__ __half g_k16 [(size_t)KVROWS * DIM];
__device__ __half g_v16 [(size_t)KVROWS * DIM];
__device__ __half g_attn16[(size_t)TOKENS * DIM];

// ---------------------------------------------------------------- helpers
__device__ __forceinline__ uint32_t smem_u32(const void* p) {
    uint32_t a;
    asm("{ .reg .u64 t; cvta.to.shared.u64 t, %1; cvt.u32.u64 %0, t; }" : "=r"(a) : "l"(p));
    return a;
}
__device__ __forceinline__ uint32_t swz(uint32_t off) { return off ^ ((off >> 3) & 0x70); }

__device__ __forceinline__ void cpasync16(uint32_t s, const void* g) {
    asm volatile("cp.async.cg.shared.global [%0], [%1], 16;" :: "r"(s), "l"(g));
}
__device__ __forceinline__ void cp_commit() {
    asm volatile("cp.async.commit_group;" ::: "memory");
}
template <int N>
__device__ __forceinline__ void cp_wait() {
    asm volatile("cp.async.wait_group %0;" :: "n"(N) : "memory");
}

__device__ __forceinline__ void ldsm_x4(uint32_t& r0, uint32_t& r1, uint32_t& r2, uint32_t& r3,
                                        uint32_t addr) {
    asm volatile("ldmatrix.sync.aligned.m8n8.x4.shared.b16 {%0,%1,%2,%3}, [%4];"
                 : "=r"(r0), "=r"(r1), "=r"(r2), "=r"(r3) : "r"(addr));
}

__device__ __forceinline__ void mma16816_f16(float* d, const uint32_t* a, const uint32_t* b) {
    asm volatile(
        "mma.sync.aligned.m16n8k16.row.col.f32.f16.f16.f32 "
        "{%0,%1,%2,%3}, {%4,%5,%6,%7}, {%8,%9}, {%0,%1,%2,%3};"
        : "+f"(d[0]), "+f"(d[1]), "+f"(d[2]), "+f"(d[3])
        : "r"(a[0]), "r"(a[1]), "r"(a[2]), "r"(a[3]), "r"(b[0]), "r"(b[1]));
}

#define GBM 128
#define GBN 128
#define NCHUNK (DIM / 64)                 // 16
#define MAT_BYTES (128 * 128)             // 16 KB
#define STAGE_BYTES (2 * MAT_BYTES)       // 32 KB
#define SMEM_DYN (3 * STAGE_BYTES)        // 96 KB -> 2 CTAs/SM

__device__ __forceinline__ void load_stage(
    uint32_t sbase, int tid, const char* A, const char* B,
    long long m0, long long n0, int chunk)
{
    const long long kbyte = (long long)chunk * 128;
#pragma unroll
    for (int i = 0; i < 4; i++) {
        const int u  = tid + i * 256;
        const int r  = u >> 3;
        const int c8 = u & 7;
        const uint32_t so = swz((uint32_t)(r * 128 + c8 * 16));
        cpasync16(sbase + so,             A + (m0 + r) * (DIM * 2) + kbyte + c8 * 16);
        cpasync16(sbase + MAT_BYTES + so, B + (n0 + r) * (DIM * 2) + kbyte + c8 * 16);
    }
}

// load one s-step's operand fragments (6 ldsm)
__device__ __forceinline__ void load_frag(
    uint32_t sA, uint32_t sB, int s,
    int a_row, int a_cofs, int b_row, int b_cofs,
    uint32_t af[2][4], uint32_t bf[8][2])
{
#pragma unroll
    for (int mt = 0; mt < 2; mt++) {
        const uint32_t off = swz((uint32_t)((a_row + mt * 16) * 128 + s * 32 + a_cofs));
        ldsm_x4(af[mt][0], af[mt][1], af[mt][2], af[mt][3], sA + off);
    }
#pragma unroll
    for (int np = 0; np < 4; np++) {
        const uint32_t off = swz((uint32_t)((b_row + np * 16) * 128 + s * 32 + b_cofs));
        uint32_t r0, r1, r2, r3;
        ldsm_x4(r0, r1, r2, r3, sB + off);
        bf[np * 2][0] = r0;     bf[np * 2][1] = r1;
        bf[np * 2 + 1][0] = r2; bf[np * 2 + 1][1] = r3;
    }
}

template <bool F16OUT>
__global__ __launch_bounds__(256, 2) void gemm_f16(
    const __half* __restrict__ A, const __half* __restrict__ B,
    void* __restrict__ Cout, const float* __restrict__ addend)
{
    extern __shared__ char dynsmem[];
    const uint32_t base = smem_u32(dynsmem);

    const int tid = threadIdx.x, lane = tid & 31, wid = tid >> 5;
    const int warp_m = wid & 3, warp_n = wid >> 2;
    const long long m0 = (long long)blockIdx.y * GBM;
    const long long n0 = (long long)blockIdx.x * GBN;
    const char* pA = (const char*)A;
    const char* pB = (const char*)B;

    float acc[2][8][4];
#pragma unroll
    for (int mt = 0; mt < 2; mt++)
#pragma unroll
        for (int nt = 0; nt < 8; nt++)
#pragma unroll
            for (int j = 0; j < 4; j++) acc[mt][nt][j] = 0.f;

    load_stage(base, tid, pA, pB, m0, n0, 0);
    cp_commit();
    load_stage(base + STAGE_BYTES, tid, pA, pB, m0, n0, 1);
    cp_commit();

    const int a_row = warp_m * 32 + (lane & 15);
    const int a_cofs = (lane & 16) ? 16 : 0;
    const int b_row = warp_n * 64 + (lane & 7) + ((lane & 16) ? 8 : 0);
    const int b_cofs = (lane & 8) ? 16 : 0;

    for (int c = 0; c < NCHUNK; ++c) {
        if (c + 2 < NCHUNK) cp_wait<1>(); else cp_wait<0>();
        __syncthreads();
        if (c + 2 < NCHUNK) {
            load_stage(base + ((c + 2) % 3) * STAGE_BYTES, tid, pA, pB, m0, n0, c + 2);
            cp_commit();
        }
        const uint32_t sA = base + (c % 3) * STAGE_BYTES;
        const uint32_t sB = sA + MAT_BYTES;

        // register-pipelined s-loop: fragments for s+1 issued before MMAs of s
        uint32_t af[2][2][4], bf[2][8][2];
        load_frag(sA, sB, 0, a_row, a_cofs, b_row, b_cofs, af[0], bf[0]);
#pragma unroll
        for (int s = 0; s < 4; s++) {
            if (s < 3)
                load_frag(sA, sB, s + 1, a_row, a_cofs, b_row, b_cofs,
                          af[(s + 1) & 1], bf[(s + 1) & 1]);
#pragma unroll
            for (int mt = 0; mt < 2; mt++)
#pragma unroll
                for (int nt = 0; nt < 8; nt++)
                    mma16816_f16(acc[mt][nt], af[s & 1][mt], bf[s & 1][nt]);
        }
    }

    const int g = lane >> 2, t = lane & 3;
#pragma unroll
    for (int mt = 0; mt < 2; mt++)
#pragma unroll
        for (int half = 0; half < 2; half++) {
            const long long row = m0 + warp_m * 32 + mt * 16 + g + half * 8;
            const long long colbase = n0 + warp_n * 64;
            if (F16OUT) {
                __half* crow = (__half*)Cout + row * DIM + colbase;
#pragma unroll
                for (int nt = 0; nt < 8; nt++)
                    *reinterpret_cast<__half2*>(crow + nt * 8 + 2 * t) =
                        __floats2half2_rn(acc[mt][nt][half * 2], acc[mt][nt][half * 2 + 1]);
            } else {
                float* crow = (float*)Cout + row * DIM + colbase;
                const float* arow = addend + row * DIM + colbase;
#pragma unroll
                for (int nt = 0; nt < 8; nt++) {
                    float2 v;
                    v.x = acc[mt][nt][half * 2];
                    v.y = acc[mt][nt][half * 2 + 1];
                    const float2 a = *reinterpret_cast<const float2*>(arow + nt * 8 + 2 * t);
                    v.x += a.x; v.y += a.y;
                    *reinterpret_cast<float2*>(crow + nt * 8 + 2 * t) = v;
                }
            }
        }
}

// ================================================================ converts
__global__ __launch_bounds__(256) void tohalf_kernel(
    const float4* __restrict__ x, __half2* __restrict__ y, int n4)
{
    const int i = blockIdx.x * blockDim.x + threadIdx.x;
    if (i >= n4) return;
    const float4 v = x[i];
    y[i * 2 + 0] = __floats2half2_rn(v.x, v.y);
    y[i * 2 + 1] = __floats2half2_rn(v.z, v.w);
}

__global__ __launch_bounds__(256) void weights_tohalf_kernel(
    const float4* __restrict__ wq, const float4* __restrict__ wk,
    const float4* __restrict__ wv, const float4* __restrict__ wo)
{
    const int i = blockIdx.x * blockDim.x + threadIdx.x;      // 0 .. 4*WN/4-1
    const int which = i >> 18;
    const int j = i & 0x3FFFF;
    const float4* src = (which == 0) ? wq : (which == 1) ? wk : (which == 2) ? wv : wo;
    const float4 v = src[j];
    __half2* y = reinterpret_cast<__half2*>(g_w16) + (size_t)i * 2;
    y[0] = __floats2half2_rn(v.x, v.y);
    y[1] = __floats2half2_rn(v.z, v.w);
}

// ================================================================ attention (fp16 I/O)
__global__ __launch_bounds__(256) void attn_kernel()
{
    const int gw   = (blockIdx.x * blockDim.x + threadIdx.x) >> 5;
    const int lane = threadIdx.x & 31;
    const int h = gw & (HEADS - 1);
    const int t = gw >> 4;

    const size_t qoff = (size_t)t * DIM + h * HDIM;
    const float2 qv = __half22float2(reinterpret_cast<const __half2*>(g_q16 + qoff)[lane]);

    float logits[NPREV];
#pragma unroll
    for (int n = 0; n < NPREV; n++) {
        const size_t koff = ((size_t)t * NPREV + n) * DIM + h * HDIM;
        const float2 kv = __half22float2(reinterpret_cast<const __half2*>(g_k16 + koff)[lane]);
        float p = qv.x * kv.x + qv.y * kv.y;
#pragma unroll
        for (int off = 16; off > 0; off >>= 1)
            p += __shfl_xor_sync(0xFFFFFFFFu, p, off);
        logits[n] = p * 0.125f;
    }

    float mx = logits[0];
#pragma unroll
    for (int n = 1; n < NPREV; n++) mx = fmaxf(mx, logits[n]);
    float w[NPREV], den = 0.f;
#pragma unroll
    for (int n = 0; n < NPREV; n++) { w[n] = __expf(logits[n] - mx); den += w[n]; }
    const float inv = 1.f / den;

    float o0 = 0.f, o1 = 0.f;
#pragma unroll
    for (int n = 0; n < NPREV; n++) {
        const size_t voff = ((size_t)t * NPREV + n) * DIM + h * HDIM;
        const float2 vv = __half22float2(reinterpret_cast<const __half2*>(g_v16 + voff)[lane]);
        o0 += w[n] * vv.x;
        o1 += w[n] * vv.y;
    }
    reinterpret_cast<__half2*>(g_attn16 + qoff)[lane] = __floats2half2_rn(o0 * inv, o1 * inv);
}

// ================================================================ launch
extern "C" void kernel_launch(void* const* d_in, const int* in_sizes, int n_in,
                              void* d_out, int out_size)
{
    const float* current = (const float*)d_in[0];
    const float* history = (const float*)d_in[1];
    const float* Wq      = (const float*)d_in[2];
    const float* Wk      = (const float*)d_in[3];
    const float* Wv      = (const float*)d_in[4];
    const float* Wo      = (const float*)d_in[5];
    float*       out     = (float*)d_out;

    __half *cur16, *hist16, *w16, *q16, *k16, *v16, *attn16;
    cudaGetSymbolAddress((void**)&cur16,  g_cur16);
    cudaGetSymbolAddress((void**)&hist16, g_hist16);
    cudaGetSymbolAddress((void**)&w16,    g_w16);
    cudaGetSymbolAddress((void**)&q16,    g_q16);
    cudaGetSymbolAddress((void**)&k16,    g_k16);
    cudaGetSymbolAddress((void**)&v16,    g_v16);
    cudaGetSymbolAddress((void**)&attn16, g_attn16);

    cudaFuncSetAttribute(gemm_f16<true>,  cudaFuncAttributeMaxDynamicSharedMemorySize, SMEM_DYN);
    cudaFuncSetAttribute(gemm_f16<false>, cudaFuncAttributeMaxDynamicSharedMemorySize, SMEM_DYN);

    const size_t WN = (size_t)DIM * DIM;

    // converts
    tohalf_kernel<<<TOKENS * DIM / 4 / 256, 256>>>((const float4*)current, (__half2*)cur16,
                                                   TOKENS * DIM / 4);
    tohalf_kernel<<<(int)((size_t)KVROWS * DIM / 4 / 256), 256>>>(
        (const float4*)history, (__half2*)hist16, (int)((size_t)KVROWS * DIM / 4));
    weights_tohalf_kernel<<<(int)(4 * WN / 4 / 256), 256>>>(
        (const float4*)Wq, (const float4*)Wk, (const float4*)Wv, (const float4*)Wo);

    // projections: q, k, v (separate kernels, 2 CTAs/SM)
    gemm_f16<true><<<dim3(DIM / GBN, TOKENS / GBM), 256, SMEM_DYN>>>(
        cur16, w16 + 0 * WN, q16, nullptr);
    gemm_f16<true><<<dim3(DIM / GBN, KVROWS / GBM), 256, SMEM_DYN>>>(
        hist16, w16 + 1 * WN, k16, nullptr);
    gemm_f16<true><<<dim3(DIM / GBN, KVROWS / GBM), 256, SMEM_DYN>>>(
        hist16, w16 + 2 * WN, v16, nullptr);

    // attention
    attn_kernel<<<(TOKENS * HEADS) / 8, 256>>>();

    // out = current + attn @ Wo^T
    gemm_f16<false><<<dim3(DIM / GBN, TOKENS / GBM), 256, SMEM_DYN>>>(
        attn16, w16 + 3 * WN, out, current);
}

// round 13
// speedup vs baseline: 1.7003x; 1.0670x over previous
#include <cuda_runtime.h>
#include <cuda_fp16.h>
#include <cstdint>
#include <cstddef>

// ---------------------------------------------------------------- problem shape
#define BATCH 4
#define SEQ   2048
#define NPREV 8
#define DIM   1024
#define HEADS 16
#define HDIM  64
#define TOKENS (BATCH * SEQ)           // 8192
#define KVROWS (TOKENS * NPREV)        // 65536

// ---------------------------------------------------------------- scratch (fp16)
__device__ __half g_cur16 [(size_t)TOKENS * DIM];
__device__ __half g_hist16[(size_t)KVROWS * DIM];
__device__ __half g_w16[4u * DIM * DIM];                 // Wq, Wk, Wv, Wo
__device__ __half g_q16 [(size_t)TOKENS * DIM];
__device__ __half g_k16 [(size_t)KVROWS * DIM];
__device__ __half g_v16 [(size_t)KVROWS * DIM];
__device__ __half g_attn16[(size_t)TOKENS * DIM];

// ---------------------------------------------------------------- helpers
__device__ __forceinline__ uint32_t smem_u32(const void* p) {
    uint32_t a;
    asm("{ .reg .u64 t; cvta.to.shared.u64 t, %1; cvt.u32.u64 %0, t; }" : "=r"(a) : "l"(p));
    return a;
}
__device__ __forceinline__ uint32_t swz(uint32_t off) { return off ^ ((off >> 3) & 0x70); }

__device__ __forceinline__ void cpasync16(uint32_t s, const void* g) {
    asm volatile("cp.async.cg.shared.global [%0], [%1], 16;" :: "r"(s), "l"(g));
}
__device__ __forceinline__ void cp_commit() {
    asm volatile("cp.async.commit_group;" ::: "memory");
}
template <int N>
__device__ __forceinline__ void cp_wait() {
    asm volatile("cp.async.wait_group %0;" :: "n"(N) : "memory");
}

__device__ __forceinline__ void ldsm_x4(uint32_t& r0, uint32_t& r1, uint32_t& r2, uint32_t& r3,
                                        uint32_t addr) {
    asm volatile("ldmatrix.sync.aligned.m8n8.x4.shared.b16 {%0,%1,%2,%3}, [%4];"
                 : "=r"(r0), "=r"(r1), "=r"(r2), "=r"(r3) : "r"(addr));
}

__device__ __forceinline__ void mma16816_f16(float* d, const uint32_t* a, const uint32_t* b) {
    asm volatile(
        "mma.sync.aligned.m16n8k16.row.col.f32.f16.f16.f32 "
        "{%0,%1,%2,%3}, {%4,%5,%6,%7}, {%8,%9}, {%0,%1,%2,%3};"
        : "+f"(d[0]), "+f"(d[1]), "+f"(d[2]), "+f"(d[3])
        : "r"(a[0]), "r"(a[1]), "r"(a[2]), "r"(a[3]), "r"(b[0]), "r"(b[1]));
}

#define GBM 128
#define GBN 128
#define NCHUNK (DIM / 64)                 // 16
#define MAT_BYTES (128 * 128)             // 16 KB
#define STAGE_BYTES (2 * MAT_BYTES)       // 32 KB
#define SMEM_DYN (3 * STAGE_BYTES)        // 96 KB -> 2 CTAs/SM

// 128 threads: 2048 x 16B per stage -> 16 cp.async per thread
__device__ __forceinline__ void load_stage(
    uint32_t sbase, int tid, const char* A, const char* B,
    long long m0, long long n0, int chunk)
{
    const long long kbyte = (long long)chunk * 128;
#pragma unroll
    for (int i = 0; i < 8; i++) {
        const int u  = tid + i * 128;     // 0..1023
        const int r  = u >> 3;            // row 0..127
        const int c8 = u & 7;             // 16B chunk within 128B row
        const uint32_t so = swz((uint32_t)(r * 128 + c8 * 16));
        cpasync16(sbase + so,             A + (m0 + r) * (DIM * 2) + kbyte + c8 * 16);
        cpasync16(sbase + MAT_BYTES + so, B + (n0 + r) * (DIM * 2) + kbyte + c8 * 16);
    }
}

// CTA 128x128, 4 warps, warp tile 64x64 (mt=4, nt=8). Ampere-style big warp tile:
// per s-step 8 ldsm feed 32 independent MMAs -> tensor pipe self-hiding.
template <bool F16OUT>
__global__ __launch_bounds__(128, 2) void gemm_f16(
    const __half* __restrict__ A, const __half* __restrict__ B,
    void* __restrict__ Cout, const float* __restrict__ addend)
{
    extern __shared__ char dynsmem[];
    const uint32_t base = smem_u32(dynsmem);

    const int tid = threadIdx.x, lane = tid & 31, wid = tid >> 5;   // wid 0..3
    const int warp_m = wid & 1;           // 64-row half
    const int warp_n = wid >> 1;          // 64-col half
    const long long m0 = (long long)blockIdx.y * GBM;
    const long long n0 = (long long)blockIdx.x * GBN;
    const char* pA = (const char*)A;
    const char* pB = (const char*)B;

    float acc[4][8][4];
#pragma unroll
    for (int mt = 0; mt < 4; mt++)
#pragma unroll
        for (int nt = 0; nt < 8; nt++)
#pragma unroll
            for (int j = 0; j < 4; j++) acc[mt][nt][j] = 0.f;

    load_stage(base, tid, pA, pB, m0, n0, 0);
    cp_commit();
    load_stage(base + STAGE_BYTES, tid, pA, pB, m0, n0, 1);
    cp_commit();

    const int a_row = warp_m * 64 + (lane & 15);
    const int a_cofs = (lane & 16) ? 16 : 0;
    const int b_row = warp_n * 64 + (lane & 7) + ((lane & 16) ? 8 : 0);
    const int b_cofs = (lane & 8) ? 16 : 0;

    for (int c = 0; c < NCHUNK; ++c) {
        if (c + 2 < NCHUNK) cp_wait<1>(); else cp_wait<0>();
        __syncthreads();
        if (c + 2 < NCHUNK) {
            load_stage(base + ((c + 2) % 3) * STAGE_BYTES, tid, pA, pB, m0, n0, c + 2);
            cp_commit();
        }
        const uint32_t sA = base + (c % 3) * STAGE_BYTES;
        const uint32_t sB = sA + MAT_BYTES;
#pragma unroll
        for (int s = 0; s < 4; s++) {
            uint32_t af[4][4], bf[8][2];
#pragma unroll
            for (int mt = 0; mt < 4; mt++) {
                const uint32_t off = swz((uint32_t)((a_row + mt * 16) * 128 + s * 32 + a_cofs));
                ldsm_x4(af[mt][0], af[mt][1], af[mt][2], af[mt][3], sA + off);
            }
#pragma unroll
            for (int np = 0; np < 4; np++) {
                const uint32_t off = swz((uint32_t)((b_row + np * 16) * 128 + s * 32 + b_cofs));
                uint32_t r0, r1, r2, r3;
                ldsm_x4(r0, r1, r2, r3, sB + off);
                bf[np * 2][0] = r0;     bf[np * 2][1] = r1;
                bf[np * 2 + 1][0] = r2; bf[np * 2 + 1][1] = r3;
            }
#pragma unroll
            for (int mt = 0; mt < 4; mt++)
#pragma unroll
                for (int nt = 0; nt < 8; nt++)
                    mma16816_f16(acc[mt][nt], af[mt], bf[nt]);
        }
    }

    const int g = lane >> 2, t = lane & 3;
#pragma unroll
    for (int mt = 0; mt < 4; mt++)
#pragma unroll
        for (int half = 0; half < 2; half++) {
            const long long row = m0 + warp_m * 64 + mt * 16 + g + half * 8;
            const long long colbase = n0 + warp_n * 64;
            if (F16OUT) {
                __half* crow = (__half*)Cout + row * DIM + colbase;
#pragma unroll
                for (int nt = 0; nt < 8; nt++)
                    *reinterpret_cast<__half2*>(crow + nt * 8 + 2 * t) =
                        __floats2half2_rn(acc[mt][nt][half * 2], acc[mt][nt][half * 2 + 1]);
            } else {
                float* crow = (float*)Cout + row * DIM + colbase;
                const float* arow = addend + row * DIM + colbase;
#pragma unroll
                for (int nt = 0; nt < 8; nt++) {
                    float2 v;
                    v.x = acc[mt][nt][half * 2];
                    v.y = acc[mt][nt][half * 2 + 1];
                    const float2 a = *reinterpret_cast<const float2*>(arow + nt * 8 + 2 * t);
                    v.x += a.x; v.y += a.y;
                    *reinterpret_cast<float2*>(crow + nt * 8 + 2 * t) = v;
                }
            }
        }
}

// ================================================================ converts
__global__ __launch_bounds__(256) void tohalf_kernel(
    const float4* __restrict__ x, __half2* __restrict__ y, int n4)
{
    const int i = blockIdx.x * blockDim.x + threadIdx.x;
    if (i >= n4) return;
    const float4 v = x[i];
    y[i * 2 + 0] = __floats2half2_rn(v.x, v.y);
    y[i * 2 + 1] = __floats2half2_rn(v.z, v.w);
}

__global__ __launch_bounds__(256) void weights_tohalf_kernel(
    const float4* __restrict__ wq, const float4* __restrict__ wk,
    const float4* __restrict__ wv, const float4* __restrict__ wo)
{
    const int i = blockIdx.x * blockDim.x + threadIdx.x;      // 0 .. 4*WN/4-1
    const int which = i >> 18;
    const int j = i & 0x3FFFF;
    const float4* src = (which == 0) ? wq : (which == 1) ? wk : (which == 2) ? wv : wo;
    const float4 v = src[j];
    __half2* y = reinterpret_cast<__half2*>(g_w16) + (size_t)i * 2;
    y[0] = __floats2half2_rn(v.x, v.y);
    y[1] = __floats2half2_rn(v.z, v.w);
}

// ================================================================ attention (fp16 I/O)
__global__ __launch_bounds__(256) void attn_kernel()
{
    const int gw   = (blockIdx.x * blockDim.x + threadIdx.x) >> 5;
    const int lane = threadIdx.x & 31;
    const int h = gw & (HEADS - 1);
    const int t = gw >> 4;

    const size_t qoff = (size_t)t * DIM + h * HDIM;
    const float2 qv = __half22float2(reinterpret_cast<const __half2*>(g_q16 + qoff)[lane]);

    float logits[NPREV];
#pragma unroll
    for (int n = 0; n < NPREV; n++) {
        const size_t koff = ((size_t)t * NPREV + n) * DIM + h * HDIM;
        const float2 kv = __half22float2(reinterpret_cast<const __half2*>(g_k16 + koff)[lane]);
        float p = qv.x * kv.x + qv.y * kv.y;
#pragma unroll
        for (int off = 16; off > 0; off >>= 1)
            p += __shfl_xor_sync(0xFFFFFFFFu, p, off);
        logits[n] = p * 0.125f;
    }

    float mx = logits[0];
#pragma unroll
    for (int n = 1; n < NPREV; n++) mx = fmaxf(mx, logits[n]);
    float w[NPREV], den = 0.f;
#pragma unroll
    for (int n = 0; n < NPREV; n++) { w[n] = __expf(logits[n] - mx); den += w[n]; }
    const float inv = 1.f / den;

    float o0 = 0.f, o1 = 0.f;
#pragma unroll
    for (int n = 0; n < NPREV; n++) {
        const size_t voff = ((size_t)t * NPREV + n) * DIM + h * HDIM;
        const float2 vv = __half22float2(reinterpret_cast<const __half2*>(g_v16 + voff)[lane]);
        o0 += w[n] * vv.x;
        o1 += w[n] * vv.y;
    }
    reinterpret_cast<__half2*>(g_attn16 + qoff)[lane] = __floats2half2_rn(o0 * inv, o1 * inv);
}

// ================================================================ launch
extern "C" void kernel_launch(void* const* d_in, const int* in_sizes, int n_in,
                              void* d_out, int out_size)
{
    const float* current = (const float*)d_in[0];
    const float* history = (const float*)d_in[1];
    const float* Wq      = (const float*)d_in[2];
    const float* Wk      = (const float*)d_in[3];
    const float* Wv      = (const float*)d_in[4];
    const float* Wo      = (const float*)d_in[5];
    float*       out     = (float*)d_out;

    __half *cur16, *hist16, *w16, *q16, *k16, *v16, *attn16;
    cudaGetSymbolAddress((void**)&cur16,  g_cur16);
    cudaGetSymbolAddress((void**)&hist16, g_hist16);
    cudaGetSymbolAddress((void**)&w16,    g_w16);
    cudaGetSymbolAddress((void**)&q16,    g_q16);
    cudaGetSymbolAddress((void**)&k16,    g_k16);
    cudaGetSymbolAddress((void**)&v16,    g_v16);
    cudaGetSymbolAddress((void**)&attn16, g_attn16);

    cudaFuncSetAttribute(gemm_f16<true>,  cudaFuncAttributeMaxDynamicSharedMemorySize, SMEM_DYN);
    cudaFuncSetAttribute(gemm_f16<false>, cudaFuncAttributeMaxDynamicSharedMemorySize, SMEM_DYN);

    const size_t WN = (size_t)DIM * DIM;

    // converts
    tohalf_kernel<<<TOKENS * DIM / 4 / 256, 256>>>((const float4*)current, (__half2*)cur16,
                                                   TOKENS * DIM / 4);
    tohalf_kernel<<<(int)((size_t)KVROWS * DIM / 4 / 256), 256>>>(
        (const float4*)history, (__half2*)hist16, (int)((size_t)KVROWS * DIM / 4));
    weights_tohalf_kernel<<<(int)(4 * WN / 4 / 256), 256>>>(
        (const float4*)Wq, (const float4*)Wk, (const float4*)Wv, (const float4*)Wo);

    // projections: q, k, v
    gemm_f16<true><<<dim3(DIM / GBN, TOKENS / GBM), 128, SMEM_DYN>>>(
        cur16, w16 + 0 * WN, q16, nullptr);
    gemm_f16<true><<<dim3(DIM / GBN, KVROWS / GBM), 128, SMEM_DYN>>>(
        hist16, w16 + 1 * WN, k16, nullptr);
    gemm_f16<true><<<dim3(DIM / GBN, KVROWS / GBM), 128, SMEM_DYN>>>(
        hist16, w16 + 2 * WN, v16, nullptr);

    // attention
    attn_kernel<<<(TOKENS * HEADS) / 8, 256>>>();

    // out = current + attn @ Wo^T
    gemm_f16<false><<<dim3(DIM / GBN, TOKENS / GBM), 128, SMEM_DYN>>>(
        attn16, w16 + 3 * WN, out, current);
}

// round 15
// speedup vs baseline: 1.9498x; 1.1467x over previous
#include <cuda_runtime.h>
#include <cuda_fp16.h>
#include <cstdint>
#include <cstddef>

// ---------------------------------------------------------------- problem shape
#define BATCH 4
#define SEQ   2048
#define NPREV 8
#define DIM   1024
#define HEADS 16
#define HDIM  64
#define TOKENS (BATCH * SEQ)           // 8192
#define KVROWS (TOKENS * NPREV)        // 65536

// ---------------------------------------------------------------- scratch (fp16)
__device__ __half g_cur16 [(size_t)TOKENS * DIM];
__device__ __half g_hist16[(size_t)KVROWS * DIM];
__device__ __half g_w16[4u * DIM * DIM];                 // Wq, (unused), Wv, Wo
__device__ __half g_wkt[(size_t)HEADS * DIM * HDIM];     // [h][j:1024][d:64] = Wk[h*64+d][j]
__device__ __half g_q16 [(size_t)TOKENS * DIM];
__device__ __half g_qp  [(size_t)HEADS * TOKENS * DIM];  // [h][t][j]
__device__ __half g_v16 [(size_t)KVROWS * DIM];
__device__ __half g_attn16[(size_t)TOKENS * DIM];

// ---------------------------------------------------------------- helpers
__device__ __forceinline__ uint32_t smem_u32(const void* p) {
    uint32_t a;
    asm("{ .reg .u64 t; cvta.to.shared.u64 t, %1; cvt.u32.u64 %0, t; }" : "=r"(a) : "l"(p));
    return a;
}
__device__ __forceinline__ uint32_t swz(uint32_t off) { return off ^ ((off >> 3) & 0x70); }

__device__ __forceinline__ void cpasync16(uint32_t s, const void* g) {
    asm volatile("cp.async.cg.shared.global [%0], [%1], 16;" :: "r"(s), "l"(g));
}
__device__ __forceinline__ void cp_commit() {
    asm volatile("cp.async.commit_group;" ::: "memory");
}
template <int N>
__device__ __forceinline__ void cp_wait() {
    asm volatile("cp.async.wait_group %0;" :: "n"(N) : "memory");
}

__device__ __forceinline__ void ldsm_x4(uint32_t& r0, uint32_t& r1, uint32_t& r2, uint32_t& r3,
                                        uint32_t addr) {
    asm volatile("ldmatrix.sync.aligned.m8n8.x4.shared.b16 {%0,%1,%2,%3}, [%4];"
                 : "=r"(r0), "=r"(r1), "=r"(r2), "=r"(r3) : "r"(addr));
}

__device__ __forceinline__ void mma16816_f16(float* d, const uint32_t* a, const uint32_t* b) {
    asm volatile(
        "mma.sync.aligned.m16n8k16.row.col.f32.f16.f16.f32 "
        "{%0,%1,%2,%3}, {%4,%5,%6,%7}, {%8,%9}, {%0,%1,%2,%3};"
        : "+f"(d[0]), "+f"(d[1]), "+f"(d[2]), "+f"(d[3])
        : "r"(a[0]), "r"(a[1]), "r"(a[2]), "r"(a[3]), "r"(b[0]), "r"(b[1]));
}

#define GBM 128
#define GBN 128
#define NCHUNK (DIM / 64)                 // 16
#define MAT_BYTES (128 * 128)             // 16 KB
#define STAGE_BYTES (2 * MAT_BYTES)       // 32 KB
#define SMEM_DYN (3 * STAGE_BYTES)        // 96 KB -> 2 CTAs/SM

__device__ __forceinline__ void load_stage(
    uint32_t sbase, int tid, const char* A, const char* B,
    long long m0, long long n0, int chunk)
{
    const long long kbyte = (long long)chunk * 128;
#pragma unroll
    for (int i = 0; i < 8; i++) {
        const int u  = tid + i * 128;
        const int r  = u >> 3;
        const int c8 = u & 7;
        const uint32_t so = swz((uint32_t)(r * 128 + c8 * 16));
        cpasync16(sbase + so,             A + (m0 + r) * (DIM * 2) + kbyte + c8 * 16);
        cpasync16(sbase + MAT_BYTES + so, B + (n0 + r) * (DIM * 2) + kbyte + c8 * 16);
    }
}

// CTA 128x128, 4 warps, warp tile 64x64 (R13 proven config)
template <bool F16OUT>
__global__ __launch_bounds__(128, 2) void gemm_f16(
    const __half* __restrict__ A, const __half* __restrict__ B,
    void* __restrict__ Cout, const float* __restrict__ addend)
{
    extern __shared__ char dynsmem[];
    const uint32_t base = smem_u32(dynsmem);

    const int tid = threadIdx.x, lane = tid & 31, wid = tid >> 5;
    const int warp_m = wid & 1;
    const int warp_n = wid >> 1;
    const long long m0 = (long long)blockIdx.y * GBM;
    const long long n0 = (long long)blockIdx.x * GBN;
    const char* pA = (const char*)A;
    const char* pB = (const char*)B;

    float acc[4][8][4];
#pragma unroll
    for (int mt = 0; mt < 4; mt++)
#pragma unroll
        for (int nt = 0; nt < 8; nt++)
#pragma unroll
            for (int j = 0; j < 4; j++) acc[mt][nt][j] = 0.f;

    load_stage(base, tid, pA, pB, m0, n0, 0);
    cp_commit();
    load_stage(base + STAGE_BYTES, tid, pA, pB, m0, n0, 1);
    cp_commit();

    const int a_row = warp_m * 64 + (lane & 15);
    const int a_cofs = (lane & 16) ? 16 : 0;
    const int b_row = warp_n * 64 + (lane & 7) + ((lane & 16) ? 8 : 0);
    const int b_cofs = (lane & 8) ? 16 : 0;

    for (int c = 0; c < NCHUNK; ++c) {
        if (c + 2 < NCHUNK) cp_wait<1>(); else cp_wait<0>();
        __syncthreads();
        if (c + 2 < NCHUNK) {
            load_stage(base + ((c + 2) % 3) * STAGE_BYTES, tid, pA, pB, m0, n0, c + 2);
            cp_commit();
        }
        const uint32_t sA = base + (c % 3) * STAGE_BYTES;
        const uint32_t sB = sA + MAT_BYTES;
#pragma unroll
        for (int s = 0; s < 4; s++) {
            uint32_t af[4][4], bf[8][2];
#pragma unroll
            for (int mt = 0; mt < 4; mt++) {
                const uint32_t off = swz((uint32_t)((a_row + mt * 16) * 128 + s * 32 + a_cofs));
                ldsm_x4(af[mt][0], af[mt][1], af[mt][2], af[mt][3], sA + off);
            }
#pragma unroll
            for (int np = 0; np < 4; np++) {
                const uint32_t off = swz((uint32_t)((b_row + np * 16) * 128 + s * 32 + b_cofs));
                uint32_t r0, r1, r2, r3;
                ldsm_x4(r0, r1, r2, r3, sB + off);
                bf[np * 2][0] = r0;     bf[np * 2][1] = r1;
                bf[np * 2 + 1][0] = r2; bf[np * 2 + 1][1] = r3;
            }
#pragma unroll
            for (int mt = 0; mt < 4; mt++)
#pragma unroll
                for (int nt = 0; nt < 8; nt++)
                    mma16816_f16(acc[mt][nt], af[mt], bf[nt]);
        }
    }

    const int g = lane >> 2, t = lane & 3;
#pragma unroll
    for (int mt = 0; mt < 4; mt++)
#pragma unroll
        for (int half = 0; half < 2; half++) {
            const long long row = m0 + warp_m * 64 + mt * 16 + g + half * 8;
            const long long colbase = n0 + warp_n * 64;
            if (F16OUT) {
                __half* crow = (__half*)Cout + row * DIM + colbase;
#pragma unroll
                for (int nt = 0; nt < 8; nt++)
                    *reinterpret_cast<__half2*>(crow + nt * 8 + 2 * t) =
                        __floats2half2_rn(acc[mt][nt][half * 2], acc[mt][nt][half * 2 + 1]);
            } else {
                float* crow = (float*)Cout + row * DIM + colbase;
                const float* arow = addend + row * DIM + colbase;
#pragma unroll
                for (int nt = 0; nt < 8; nt++) {
                    float2 v;
                    v.x = acc[mt][nt][half * 2];
                    v.y = acc[mt][nt][half * 2 + 1];
                    const float2 a = *reinterpret_cast<const float2*>(arow + nt * 8 + 2 * t);
                    v.x += a.x; v.y += a.y;
                    *reinterpret_cast<float2*>(crow + nt * 8 + 2 * t) = v;
                }
            }
        }
}

// ================================================================ qp GEMM (K=64, batched heads)
// grid (8, 64, 16): head h tile: qp[h][m0..m0+128][n0..n0+128] =
//   q[m0.., h*64..] (128x64) @ wkt_h[n0.., :] (128x64)^T. Single K-chunk, 4 s-steps.
__global__ __launch_bounds__(128, 2) void gemm_qp()
{
    __shared__ char sm[2 * MAT_BYTES];       // A 16KB + B 16KB
    const uint32_t sA = smem_u32(sm);
    const uint32_t sB = sA + MAT_BYTES;

    const int tid = threadIdx.x, lane = tid & 31, wid = tid >> 5;
    const int warp_m = wid & 1, warp_n = wid >> 1;
    const int h = blockIdx.z;
    const long long m0 = (long long)blockIdx.y * 128;
    const long long n0 = (long long)blockIdx.x * 128;

    const char* A = (const char*)g_q16 + m0 * (DIM * 2) + h * 128;         // 128B rows, lda 2KB
    const char* B = (const char*)g_wkt + (size_t)h * (DIM * HDIM * 2)
                    + n0 * (HDIM * 2);                                     // 128B rows, ldb 128B
#pragma unroll
    for (int i = 0; i < 8; i++) {
        const int u = tid + i * 128;
        const int r = u >> 3, c8 = u & 7;
        const uint32_t so = swz((uint32_t)(r * 128 + c8 * 16));
        cpasync16(sA + so, A + (long long)r * (DIM * 2) + c8 * 16);
        cpasync16(sB + so, B + r * 128 + c8 * 16);
    }
    cp_commit();

    float acc[4][8][4];
#pragma unroll
    for (int mt = 0; mt < 4; mt++)
#pragma unroll
        for (int nt = 0; nt < 8; nt++)
#pragma unroll
            for (int j = 0; j < 4; j++) acc[mt][nt][j] = 0.f;

    const int a_row = warp_m * 64 + (lane & 15);
    const int a_cofs = (lane & 16) ? 16 : 0;
    const int b_row = warp_n * 64 + (lane & 7) + ((lane & 16) ? 8 : 0);
    const int b_cofs = (lane & 8) ? 16 : 0;

    cp_wait<0>();
    __syncthreads();

#pragma unroll
    for (int s = 0; s < 4; s++) {
        uint32_t af[4][4], bf[8][2];
#pragma unroll
        for (int mt = 0; mt < 4; mt++) {
            const uint32_t off = swz((uint32_t)((a_row + mt * 16) * 128 + s * 32 + a_cofs));
            ldsm_x4(af[mt][0], af[mt][1], af[mt][2], af[mt][3], sA + off);
        }
#pragma unroll
        for (int np = 0; np < 4; np++) {
            const uint32_t off = swz((uint32_t)((b_row + np * 16) * 128 + s * 32 + b_cofs));
            uint32_t r0, r1, r2, r3;
            ldsm_x4(r0, r1, r2, r3, sB + off);
            bf[np * 2][0] = r0;     bf[np * 2][1] = r1;
            bf[np * 2 + 1][0] = r2; bf[np * 2 + 1][1] = r3;
        }
#pragma unroll
        for (int mt = 0; mt < 4; mt++)
#pragma unroll
            for (int nt = 0; nt < 8; nt++)
                mma16816_f16(acc[mt][nt], af[mt], bf[nt]);
    }

    __half* C = g_qp + ((size_t)h * TOKENS + m0) * DIM + n0;
    const int g = lane >> 2, t = lane & 3;
#pragma unroll
    for (int mt = 0; mt < 4; mt++)
#pragma unroll
        for (int half = 0; half < 2; half++) {
            const long long row = warp_m * 64 + mt * 16 + g + half * 8;
            __half* crow = C + row * DIM + warp_n * 64;
#pragma unroll
            for (int nt = 0; nt < 8; nt++)
                *reinterpret_cast<__half2*>(crow + nt * 8 + 2 * t) =
                    __floats2half2_rn(acc[mt][nt][half * 2], acc[mt][nt][half * 2 + 1]);
        }
}

// ================================================================ converts
__global__ __launch_bounds__(256) void tohalf_kernel(
    const float4* __restrict__ x, __half2* __restrict__ y, int n4)
{
    const int i = blockIdx.x * blockDim.x + threadIdx.x;
    if (i >= n4) return;
    const float4 v = x[i];
    y[i * 2 + 0] = __floats2half2_rn(v.x, v.y);
    y[i * 2 + 1] = __floats2half2_rn(v.z, v.w);
}

__global__ __launch_bounds__(256) void weights_tohalf_kernel(
    const float4* __restrict__ wq, const float4* __restrict__ wv,
    const float4* __restrict__ wo)
{
    const int i = blockIdx.x * blockDim.x + threadIdx.x;      // 0 .. 3*WN/4-1
    const int which = i >> 18;                                 // WN/4 = 262144
    const int j = i & 0x3FFFF;
    const float4* src = (which == 0) ? wq : (which == 1) ? wv : wo;
    const int slot = (which == 0) ? 0 : (which == 1) ? 2 : 3;  // keep 4-slot layout
    const float4 v = src[j];
    __half2* y = reinterpret_cast<__half2*>(g_w16) + ((size_t)slot << 18) * 2 + (size_t)j * 2;
    y[0] = __floats2half2_rn(v.x, v.y);
    y[1] = __floats2half2_rn(v.z, v.w);
}

// wkt[h][j][d] = Wk[h*64+d][j]
__global__ __launch_bounds__(256) void wkt_kernel(const float* __restrict__ Wk)
{
    const int idx = blockIdx.x * blockDim.x + threadIdx.x;   // 1M
    const int h = idx >> 16;
    const int j = (idx >> 6) & 1023;
    const int d = idx & 63;
    g_wkt[idx] = __float2half(Wk[(h * HDIM + d) * DIM + j]);
}

// ================================================================ fused attention
// CTA per token, 512 threads (warp = head). logits = qp[h,t,:]·hist16[t,n,:],
// softmax, then mix projected V head-slices. Output attn16 (small!).
__global__ __launch_bounds__(512) void attn_fused()
{
    __shared__ __half2 hist2[NPREV * 512];      // 16KB

    const int t = blockIdx.x;
    const int tid = threadIdx.x;
    const int lane = tid & 31;
    const int h = tid >> 5;                     // 0..15

    {   // stage hist16[t]: 8192 halfs = 1024 uint4
        const uint4* src = reinterpret_cast<const uint4*>(g_hist16 + (size_t)t * NPREV * DIM);
        uint4* dst = reinterpret_cast<uint4*>(hist2);
        dst[tid]       = src[tid];
        dst[tid + 512] = src[tid + 512];
    }
    __syncthreads();

    const __half2* qp2 = reinterpret_cast<const __half2*>(g_qp + ((size_t)h * TOKENS + t) * DIM);
    __half2 q2[16];
#pragma unroll
    for (int i = 0; i < 16; i++) q2[i] = qp2[lane + 32 * i];

    float logits[NPREV];
#pragma unroll
    for (int n = 0; n < NPREV; n++) {
        float p = 0.f;
#pragma unroll
        for (int i = 0; i < 16; i++) {
            const float2 a = __half22float2(q2[i]);
            const float2 b = __half22float2(hist2[n * 512 + lane + 32 * i]);
            p += a.x * b.x + a.y * b.y;
        }
#pragma unroll
        for (int off = 16; off > 0; off >>= 1)
            p += __shfl_xor_sync(0xFFFFFFFFu, p, off);
        logits[n] = p * 0.125f;
    }

    float mx = logits[0];
#pragma unroll
    for (int n = 1; n < NPREV; n++) mx = fmaxf(mx, logits[n]);
    float w[NPREV], den = 0.f;
#pragma unroll
    for (int n = 0; n < NPREV; n++) { w[n] = __expf(logits[n] - mx); den += w[n]; }
    const float inv = 1.f / den;

    // V mix: lane owns dims {2*lane, 2*lane+1} of head slice -> half2 idx h*32+lane
    float ox = 0.f, oy = 0.f;
    const __half2* v2 = reinterpret_cast<const __half2*>(g_v16);
#pragma unroll
    for (int n = 0; n < NPREV; n++) {
        const float2 vv = __half22float2(v2[((size_t)t * NPREV + n) * 512 + h * 32 + lane]);
        ox += w[n] * vv.x;
        oy += w[n] * vv.y;
    }
    reinterpret_cast<__half2*>(g_attn16)[(size_t)t * 512 + h * 32 + lane] =
        __floats2half2_rn(ox * inv, oy * inv);
}

// ================================================================ launch
extern "C" void kernel_launch(void* const* d_in, const int* in_sizes, int n_in,
                              void* d_out, int out_size)
{
    const float* current = (const float*)d_in[0];
    const float* history = (const float*)d_in[1];
    const float* Wq      = (const float*)d_in[2];
    const float* Wk      = (const float*)d_in[3];
    const float* Wv      = (const float*)d_in[4];
    const float* Wo      = (const float*)d_in[5];
    float*       out     = (float*)d_out;

    __half *cur16, *hist16, *w16, *q16, *v16, *attn16;
    cudaGetSymbolAddress((void**)&cur16,  g_cur16);
    cudaGetSymbolAddress((void**)&hist16, g_hist16);
    cudaGetSymbolAddress((void**)&w16,    g_w16);
    cudaGetSymbolAddress((void**)&q16,    g_q16);
    cudaGetSymbolAddress((void**)&v16,    g_v16);
    cudaGetSymbolAddress((void**)&attn16, g_attn16);

    cudaFuncSetAttribute(gemm_f16<true>,  cudaFuncAttributeMaxDynamicSharedMemorySize, SMEM_DYN);
    cudaFuncSetAttribute(gemm_f16<false>, cudaFuncAttributeMaxDynamicSharedMemorySize, SMEM_DYN);

    const size_t WN = (size_t)DIM * DIM;

    // converts
    tohalf_kernel<<<TOKENS * DIM / 4 / 256, 256>>>((const float4*)current, (__half2*)cur16,
                                                   TOKENS * DIM / 4);
    tohalf_kernel<<<(int)((size_t)KVROWS * DIM / 4 / 256), 256>>>(
        (const float4*)history, (__half2*)hist16, (int)((size_t)KVROWS * DIM / 4));
    weights_tohalf_kernel<<<(int)(3 * WN / 4 / 256), 256>>>(
        (const float4*)Wq, (const float4*)Wv, (const float4*)Wo);
    wkt_kernel<<<(int)(WN / 256), 256>>>(Wk);

    // q = current @ Wq^T
    gemm_f16<true><<<dim3(DIM / GBN, TOKENS / GBM), 128, SMEM_DYN>>>(
        cur16, w16 + 0 * WN, q16, nullptr);

    // qp per head (replaces the 137 GF k-projection)
    gemm_qp<<<dim3(DIM / 128, TOKENS / 128, HEADS), 128>>>();

    // v = hist @ Wv^T
    gemm_f16<true><<<dim3(DIM / GBN, KVROWS / GBM), 128, SMEM_DYN>>>(
        hist16, w16 + 2 * WN, v16, nullptr);

    // fused logits + softmax + V mix
    attn_fused<<<TOKENS, 512>>>();

    // out = current + attn @ Wo^T
    gemm_f16<false><<<dim3(DIM / GBN, TOKENS / GBM), 128, SMEM_DYN>>>(
        attn16, w16 + 3 * WN, out, current);
}